// round 4
// baseline (speedup 1.0000x reference)
#include <cuda_runtime.h>

// ---------------------------------------------------------------------------
// AttentionBlock: GroupNorm -> QKV 1x1 conv -> MHA (4 heads, d=64, L=4096)
//                 -> proj 1x1 conv -> residual
// B=4, C=256, H=W=64, fp32 throughout.
// ---------------------------------------------------------------------------

namespace {
constexpr int B_  = 4;
constexpr int C_  = 256;
constexpr int L_  = 4096;      // H*W
constexpr int G_  = 32;        // groups
constexpr int NH_ = 4;         // heads
constexpr int D_  = 64;        // head dim
constexpr int CPG_ = C_ / G_;  // 8 channels per group
constexpr int SQ_ = 68;        // smem row stride (float4-aligned, conflict-friendly)
}

// Scratch (static device globals; no runtime allocation allowed)
__device__ float g_h[B_ * C_ * L_];          // normalized input   (16.8 MB)
__device__ float g_qkv[B_ * 3 * C_ * L_];    // qkv activations    (50.3 MB)
__device__ float g_o[B_ * C_ * L_];          // attention output   (16.8 MB)
__device__ float g_mean[B_ * G_];
__device__ float g_rstd[B_ * G_];

// ---------------------------------------------------------------------------
// 1) GroupNorm statistics: one block per (batch, group). Group data is a
//    contiguous run of CPG_*L_ = 32768 floats.
// ---------------------------------------------------------------------------
__global__ void gn_stats_kernel(const float* __restrict__ x) {
    const int bg = blockIdx.x;
    const float4* p = reinterpret_cast<const float4*>(x) + (size_t)bg * (CPG_ * L_ / 4);
    float s = 0.f, ss = 0.f;
    for (int i = threadIdx.x; i < CPG_ * L_ / 4; i += blockDim.x) {
        float4 v = p[i];
        s  += v.x + v.y + v.z + v.w;
        ss += v.x * v.x + v.y * v.y + v.z * v.z + v.w * v.w;
    }
#pragma unroll
    for (int o = 16; o > 0; o >>= 1) {
        s  += __shfl_xor_sync(0xffffffffu, s, o);
        ss += __shfl_xor_sync(0xffffffffu, ss, o);
    }
    __shared__ float sh_s[8], sh_ss[8];
    const int w = threadIdx.x >> 5;
    if ((threadIdx.x & 31) == 0) { sh_s[w] = s; sh_ss[w] = ss; }
    __syncthreads();
    if (threadIdx.x == 0) {
        float S = 0.f, SS = 0.f;
#pragma unroll
        for (int i = 0; i < 8; i++) { S += sh_s[i]; SS += sh_ss[i]; }
        const float inv = 1.f / (float)(CPG_ * L_);
        const float mean = S * inv;
        const float var  = SS * inv - mean * mean;
        g_mean[bg] = mean;
        g_rstd[bg] = rsqrtf(var + 1e-5f);
    }
}

// ---------------------------------------------------------------------------
// 2) Apply GroupNorm affine: g_h = (x - mean) * rstd * w + b  (float4 vec)
// ---------------------------------------------------------------------------
__global__ void gn_apply_kernel(const float* __restrict__ x,
                                const float* __restrict__ w,
                                const float* __restrict__ bvec) {
    const int i4 = blockIdx.x * blockDim.x + threadIdx.x;   // float4 index
    const int c  = (i4 >> 10) & (C_ - 1);                   // L_/4 = 1024 per channel
    const int bg = i4 >> 13;                                // 8192 float4 per group
    const float mean = g_mean[bg];
    const float sc = g_rstd[bg] * w[c];
    const float sh = bvec[c] - mean * sc;
    float4 v = reinterpret_cast<const float4*>(x)[i4];
    v.x = v.x * sc + sh;  v.y = v.y * sc + sh;
    v.z = v.z * sc + sh;  v.w = v.w * sc + sh;
    reinterpret_cast<float4*>(g_h)[i4] = v;
}

// ---------------------------------------------------------------------------
// 3) Tiled SGEMM with bias (+ optional residual):
//    C[b][m][n] = bias[m] + sum_k A[m][k] * B[b][k][n]  (+ R[b][m][n])
//    BM=BN=64, BK=16, 256 threads, 4x4 microtile, float4 smem reads.
// ---------------------------------------------------------------------------
__global__ void __launch_bounds__(256) sgemm_kernel(
    const float* __restrict__ A, const float* __restrict__ Bmat,
    const float* __restrict__ bias, const float* __restrict__ resid,
    float* __restrict__ Cmat, int M, int N, int K,
    size_t strideB, size_t strideC, size_t strideR)
{
    __shared__ float As[16][64];
    __shared__ float Bs[16][64];
    const int bz = blockIdx.z;
    const float* Bp = Bmat + (size_t)bz * strideB;
    float*       Cp = Cmat + (size_t)bz * strideC;
    const float* Rp = resid ? resid + (size_t)bz * strideR : nullptr;
    const int m0 = blockIdx.y * 64;
    const int n0 = blockIdx.x * 64;
    const int tid = threadIdx.x;
    const int tx = tid & 15, ty = tid >> 4;
    const int arow = tid >> 2;            // 0..63 (m within tile)
    const int acol = (tid & 3) << 2;      // 0..12 (k chunk)
    const int brow = tid >> 4;            // 0..15 (k)
    const int bcol = (tid & 15) << 2;     // 0..60 (n chunk)

    float acc[4][4] = {};
    for (int k0 = 0; k0 < K; k0 += 16) {
        float4 av = *reinterpret_cast<const float4*>(A + (size_t)(m0 + arow) * K + k0 + acol);
        As[acol + 0][arow] = av.x;
        As[acol + 1][arow] = av.y;
        As[acol + 2][arow] = av.z;
        As[acol + 3][arow] = av.w;
        *reinterpret_cast<float4*>(&Bs[brow][bcol]) =
            *reinterpret_cast<const float4*>(Bp + (size_t)(k0 + brow) * N + n0 + bcol);
        __syncthreads();
#pragma unroll
        for (int kk = 0; kk < 16; kk++) {
            float4 a4 = *reinterpret_cast<const float4*>(&As[kk][ty * 4]);
            float4 b4 = *reinterpret_cast<const float4*>(&Bs[kk][tx * 4]);
            const float a[4]  = {a4.x, a4.y, a4.z, a4.w};
            const float bb[4] = {b4.x, b4.y, b4.z, b4.w};
#pragma unroll
            for (int i = 0; i < 4; i++)
#pragma unroll
                for (int j = 0; j < 4; j++) acc[i][j] += a[i] * bb[j];
        }
        __syncthreads();
    }
#pragma unroll
    for (int i = 0; i < 4; i++) {
        const int m = m0 + ty * 4 + i;
        const float bi = bias[m];
        float4 r = make_float4(acc[i][0] + bi, acc[i][1] + bi,
                               acc[i][2] + bi, acc[i][3] + bi);
        const size_t off = (size_t)m * N + n0 + tx * 4;
        if (Rp) {
            float4 rr = *reinterpret_cast<const float4*>(Rp + off);
            r.x += rr.x; r.y += rr.y; r.z += rr.z; r.w += rr.w;
        }
        *reinterpret_cast<float4*>(Cp + off) = r;
    }
}

// ---------------------------------------------------------------------------
// 4) Flash attention, fp32. One block = (batch, head, 64-query tile).
//    q/k/v live in g_qkv with (channel, L) layout: element (l, dd) of head h
//    is at channel (sel*256 + h*64 + dd), position l. 256 threads, 4x4
//    microtile for both S (l x m) and O (l x dd).
// ---------------------------------------------------------------------------
__global__ void __launch_bounds__(256) attn_kernel(const float* __restrict__ qkv,
                                                   float* __restrict__ out) {
    extern __shared__ float sm[];
    float* Qs   = sm;                 // [64][SQ_]  (dd, l), prescaled by 1/8
    float* Ks   = Qs + 64 * SQ_;      // [64][SQ_]  (dd, m)
    float* Ps   = Ks + 64 * SQ_;      // [64][SQ_]  (l, m); reused as staging (dd, l)
    float* Vt   = Ps + 64 * SQ_;      // [64][SQ_]  (m, dd)  -- V transposed
    float* Mrow = Vt + 64 * SQ_;      // [64]
    float* Srow = Mrow + 64;          // [64]
    float* Crow = Srow + 64;          // [64]

    const int l0   = blockIdx.x * 64;
    const int head = blockIdx.y;
    const int b    = blockIdx.z;
    const float* qp = qkv + ((size_t)b * (3 * C_) + head * D_) * L_;
    const float* kp = qp + (size_t)C_ * L_;
    const float* vp = qp + (size_t)(2 * C_) * L_;
    float* op = out + ((size_t)b * C_ + head * D_) * L_;

    const int tid = threadIdx.x;
    const int tx = tid & 15;    // dd / m microtile column group
    const int ty = tid >> 4;    // l microtile row group

    // Load Q tile (64 dd x 64 l), prescale by d^-0.5 = 1/8.
#pragma unroll
    for (int i = 0; i < 4; i++) {
        const int e = tid + i * 256;
        const int dd = e >> 4;
        const int l4 = (e & 15) << 2;
        float4 v = *reinterpret_cast<const float4*>(qp + (size_t)dd * L_ + l0 + l4);
        float* q = Qs + dd * SQ_ + l4;
        q[0] = v.x * 0.125f; q[1] = v.y * 0.125f;
        q[2] = v.z * 0.125f; q[3] = v.w * 0.125f;
    }
    if (tid < 64) { Mrow[tid] = -3.0e38f; Srow[tid] = 0.f; }
    float acc[4][4] = {};
    __syncthreads();

    for (int m0 = 0; m0 < L_; m0 += 64) {
        // Load K tile (dd, m) and V tile transposed (m, dd).
#pragma unroll
        for (int i = 0; i < 4; i++) {
            const int e = tid + i * 256;
            const int dd = e >> 4;
            const int l4 = (e & 15) << 2;
            *reinterpret_cast<float4*>(Ks + dd * SQ_ + l4) =
                *reinterpret_cast<const float4*>(kp + (size_t)dd * L_ + m0 + l4);
            float4 v = *reinterpret_cast<const float4*>(vp + (size_t)dd * L_ + m0 + l4);
            Vt[(l4 + 0) * SQ_ + dd] = v.x;
            Vt[(l4 + 1) * SQ_ + dd] = v.y;
            Vt[(l4 + 2) * SQ_ + dd] = v.z;
            Vt[(l4 + 3) * SQ_ + dd] = v.w;
        }
        __syncthreads();

        // S = (Q/8)^T K : 64x64 tile, reduction over dd.
        float s[4][4] = {};
#pragma unroll 16
        for (int kk = 0; kk < 64; kk++) {
            float4 a4 = *reinterpret_cast<const float4*>(Qs + kk * SQ_ + ty * 4);
            float4 b4 = *reinterpret_cast<const float4*>(Ks + kk * SQ_ + tx * 4);
            const float a[4]  = {a4.x, a4.y, a4.z, a4.w};
            const float bb[4] = {b4.x, b4.y, b4.z, b4.w};
#pragma unroll
            for (int i = 0; i < 4; i++)
#pragma unroll
                for (int j = 0; j < 4; j++) s[i][j] += a[i] * bb[j];
        }
#pragma unroll
        for (int i = 0; i < 4; i++)
            *reinterpret_cast<float4*>(Ps + (ty * 4 + i) * SQ_ + tx * 4) =
                make_float4(s[i][0], s[i][1], s[i][2], s[i][3]);
        __syncthreads();

        // Online softmax: 4 threads per row (quad), 16 entries each.
        {
            const int l = tid >> 2;
            const int base = (tid & 3) << 4;
            float* pr = Ps + l * SQ_ + base;
            float mx = pr[0];
#pragma unroll
            for (int q = 1; q < 16; q++) mx = fmaxf(mx, pr[q]);
            mx = fmaxf(mx, __shfl_xor_sync(0xffffffffu, mx, 1));
            mx = fmaxf(mx, __shfl_xor_sync(0xffffffffu, mx, 2));
            const float Mold = Mrow[l];
            const float Mnew = fmaxf(Mold, mx);
            float sum = 0.f;
#pragma unroll
            for (int q = 0; q < 16; q++) {
                const float e = __expf(pr[q] - Mnew);
                pr[q] = e;
                sum += e;
            }
            sum += __shfl_xor_sync(0xffffffffu, sum, 1);
            sum += __shfl_xor_sync(0xffffffffu, sum, 2);
            if ((tid & 3) == 0) {
                const float corr = __expf(Mold - Mnew);
                Crow[l] = corr;
                Srow[l] = Srow[l] * corr + sum;
                Mrow[l] = Mnew;
            }
        }
        __syncthreads();

        // Rescale accumulators, then O += P @ V.
        const float c0 = Crow[ty * 4 + 0], c1 = Crow[ty * 4 + 1];
        const float c2 = Crow[ty * 4 + 2], c3 = Crow[ty * 4 + 3];
#pragma unroll
        for (int j = 0; j < 4; j++) {
            acc[0][j] *= c0; acc[1][j] *= c1;
            acc[2][j] *= c2; acc[3][j] *= c3;
        }
#pragma unroll 8
        for (int m = 0; m < 64; m++) {
            float4 v4 = *reinterpret_cast<const float4*>(Vt + m * SQ_ + tx * 4);
            const float p0 = Ps[(ty * 4 + 0) * SQ_ + m];
            const float p1 = Ps[(ty * 4 + 1) * SQ_ + m];
            const float p2 = Ps[(ty * 4 + 2) * SQ_ + m];
            const float p3 = Ps[(ty * 4 + 3) * SQ_ + m];
            acc[0][0] += p0 * v4.x; acc[0][1] += p0 * v4.y; acc[0][2] += p0 * v4.z; acc[0][3] += p0 * v4.w;
            acc[1][0] += p1 * v4.x; acc[1][1] += p1 * v4.y; acc[1][2] += p1 * v4.z; acc[1][3] += p1 * v4.w;
            acc[2][0] += p2 * v4.x; acc[2][1] += p2 * v4.y; acc[2][2] += p2 * v4.z; acc[2][3] += p2 * v4.w;
            acc[3][0] += p3 * v4.x; acc[3][1] += p3 * v4.y; acc[3][2] += p3 * v4.z; acc[3][3] += p3 * v4.w;
        }
        __syncthreads();
    }

    // Normalize by row sums and write out in (channel, L) layout via smem stage.
    float inv[4];
#pragma unroll
    for (int i = 0; i < 4; i++) inv[i] = 1.f / Srow[ty * 4 + i];
#pragma unroll
    for (int i = 0; i < 4; i++)
#pragma unroll
        for (int j = 0; j < 4; j++)
            Ps[(tx * 4 + j) * SQ_ + ty * 4 + i] = acc[i][j] * inv[i];  // stage (dd, l)
    __syncthreads();
#pragma unroll
    for (int i = 0; i < 4; i++) {
        const int e = tid + i * 256;
        const int dd = e >> 4;
        const int l4 = (e & 15) << 2;
        const float* src = Ps + dd * SQ_ + l4;
        *reinterpret_cast<float4*>(op + (size_t)dd * L_ + l0 + l4) =
            make_float4(src[0], src[1], src[2], src[3]);
    }
}

// ---------------------------------------------------------------------------
// Host launcher (graph-capturable: kernel launches + immediate host API only)
// ---------------------------------------------------------------------------
extern "C" void kernel_launch(void* const* d_in, const int* in_sizes, int n_in,
                              void* d_out, int out_size) {
    (void)in_sizes; (void)n_in; (void)out_size;
    const float* x      = (const float*)d_in[0];
    const float* gn_w   = (const float*)d_in[1];
    const float* gn_b   = (const float*)d_in[2];
    const float* qkv_w  = (const float*)d_in[3];
    const float* qkv_b  = (const float*)d_in[4];
    const float* proj_w = (const float*)d_in[5];
    const float* proj_b = (const float*)d_in[6];
    float* out = (float*)d_out;

    void *ph, *pqkv, *po;
    cudaGetSymbolAddress(&ph, g_h);
    cudaGetSymbolAddress(&pqkv, g_qkv);
    cudaGetSymbolAddress(&po, g_o);
    float* h      = (float*)ph;
    float* qkvbuf = (float*)pqkv;
    float* obuf   = (float*)po;

    // 1) GroupNorm
    gn_stats_kernel<<<B_ * G_, 256>>>(x);
    gn_apply_kernel<<<(B_ * C_ * L_ / 4) / 256, 256>>>(x, gn_w, gn_b);

    // 2) QKV: (768 x 256) @ (256 x 4096) per batch
    sgemm_kernel<<<dim3(L_ / 64, (3 * C_) / 64, B_), 256>>>(
        qkv_w, h, qkv_b, nullptr, qkvbuf, 3 * C_, L_, C_,
        (size_t)C_ * L_, (size_t)(3 * C_) * L_, 0);

    // 3) Attention (flash, fp32)
    constexpr int ATTN_SMEM = (4 * 64 * SQ_ + 192) * (int)sizeof(float);  // 70400 B
    cudaFuncSetAttribute(attn_kernel, cudaFuncAttributeMaxDynamicSharedMemorySize, ATTN_SMEM);
    attn_kernel<<<dim3(L_ / 64, NH_, B_), 256, ATTN_SMEM>>>(qkvbuf, obuf);

    // 4) Proj + bias + residual: (256 x 256) @ (256 x 4096) per batch
    sgemm_kernel<<<dim3(L_ / 64, C_ / 64, B_), 256>>>(
        proj_w, obuf, proj_b, x, out, C_, L_, C_,
        (size_t)C_ * L_, (size_t)C_ * L_, (size_t)C_ * L_);
}